// round 5
// baseline (speedup 1.0000x reference)
#include <cuda_runtime.h>

#define TPB 128   // threads per block; each thread handles 2 batch rows

typedef unsigned long long f2;   // packed (lane0, lane1) f32x2

__device__ __forceinline__ f2 f2pack(float a, float b) {
    f2 r; asm("mov.b64 %0,{%1,%2};" : "=l"(r) : "f"(a), "f"(b)); return r;
}
__device__ __forceinline__ f2 f2dup(float a) { return f2pack(a, a); }
__device__ __forceinline__ void f2unpack(f2 v, float& a, float& b) {
    asm("mov.b64 {%0,%1},%2;" : "=f"(a), "=f"(b) : "l"(v));
}
__device__ __forceinline__ f2 f2mul(f2 a, f2 b) {
    f2 r; asm("mul.rn.f32x2 %0,%1,%2;" : "=l"(r) : "l"(a), "l"(b)); return r;
}
__device__ __forceinline__ f2 f2add(f2 a, f2 b) {
    f2 r; asm("add.rn.f32x2 %0,%1,%2;" : "=l"(r) : "l"(a), "l"(b)); return r;
}
__device__ __forceinline__ f2 f2sub(f2 a, f2 b) {
    f2 r; asm("sub.rn.f32x2 %0,%1,%2;" : "=l"(r) : "l"(a), "l"(b)); return r;
}
__device__ __forceinline__ f2 f2fma(f2 a, f2 b, f2 c) {
    f2 r; asm("fma.rn.f32x2 %0,%1,%2,%3;" : "=l"(r) : "l"(a), "l"(b), "l"(c)); return r;
}
__device__ __forceinline__ f2 f2neg(f2 a) {
    f2 r; asm("xor.b64 %0,%1,%2;" : "=l"(r) : "l"(a), "l"(0x8000000080000000ULL)); return r;
}
__device__ __forceinline__ float fsqrt_ap(float x) {
    float r; asm("sqrt.approx.f32 %0,%1;" : "=f"(r) : "f"(x)); return r;
}
__device__ __forceinline__ float frsqrt_ap(float x) {
    float r; asm("rsqrt.approx.f32 %0,%1;" : "=f"(r) : "f"(x)); return r;
}

struct C2 { f2 r, i; };
struct MC { f2 ar, ai, nai, cr, ci, nci, ct, st, nst; };

// data-dependent mode: two lanes, independent angles
__device__ __forceinline__ MC mkmc(float tha, float thb, float pha, float phb) {
    float sta, cta, stb, ctb, spa, cpa, spb, cpb;
    __sincosf(tha, &sta, &cta); __sincosf(thb, &stb, &ctb);
    __sincosf(pha, &spa, &cpa); __sincosf(phb, &spb, &cpb);
    MC m;
    m.ct = f2pack(cta, ctb); m.st = f2pack(sta, stb);
    f2 cp = f2pack(cpa, cpb), sp = f2pack(spa, spb);
    m.ar = f2mul(cp, m.ct); m.ai = f2mul(sp, m.ct);
    m.cr = f2mul(cp, m.st); m.ci = f2mul(sp, m.st);
    m.nai = f2neg(m.ai); m.nci = f2neg(m.ci); m.nst = f2neg(m.st);
    return m;
}

// full complex-complex Givens rotation on packed state
__device__ __forceinline__ void rot_cc(C2& pi, C2& pj, const MC& m) {
    f2 nir = f2fma(m.ar, pi.r, f2fma(m.nai, pi.i, f2mul(m.nst, pj.r)));
    f2 nii = f2fma(m.ar, pi.i, f2fma(m.ai,  pi.r, f2mul(m.nst, pj.i)));
    f2 njr = f2fma(m.cr, pi.r, f2fma(m.nci, pi.i, f2mul(m.ct,  pj.r)));
    f2 nji = f2fma(m.cr, pi.i, f2fma(m.ci,  pi.r, f2mul(m.ct,  pj.i)));
    pi.r = nir; pi.i = nii; pj.r = njr; pj.i = nji;
}
// pi complex, pj == 0 -> both complex
__device__ __forceinline__ void rot_c0(C2& pi, C2& pj, const MC& m) {
    f2 nir = f2fma(m.ar, pi.r, f2mul(m.nai, pi.i));
    f2 nii = f2fma(m.ar, pi.i, f2mul(m.ai,  pi.r));
    pj.r   = f2fma(m.cr, pi.r, f2mul(m.nci, pi.i));
    pj.i   = f2fma(m.cr, pi.i, f2mul(m.ci,  pi.r));
    pi.r = nir; pi.i = nii;
}
// pi real w, pj complex -> both complex
__device__ __forceinline__ void rot_rc(f2 w, C2& pi, C2& pj, const MC& m) {
    pi.r = f2fma(m.ar, w, f2mul(m.nst, pj.r));
    pi.i = f2fma(m.ai, w, f2mul(m.nst, pj.i));
    f2 njr = f2fma(m.cr, w, f2mul(m.ct, pj.r));
    f2 nji = f2fma(m.ci, w, f2mul(m.ct, pj.i));
    pj.r = njr; pj.i = nji;
}

__global__ __launch_bounds__(TPB, 7)
void bqnn_main(const float* __restrict__ x,
               const float* __restrict__ pphi,
               const float* __restrict__ pth,
               const float* __restrict__ ink,
               const float* __restrict__ inb,
               float* __restrict__ out,
               int batch) {
    __shared__ float sout[TPB * 30];
    __shared__ f2 spre[5 + 4 * 9];   // [0..4]=prelude u0,u1,u2,v3,v4; 4 MCs of 9
    const int t = threadIdx.x;
    const int base = blockIdx.x * (TPB * 2);
    const int r0 = base + 2 * t;

    // ---- per-block uniform precompute (threads 0..4) ----
    if (t < 4) {
        float th = __ldg(pth + 4 + t), ph = __ldg(pphi + t);
        float st, ct, sp, cp;
        __sincosf(th, &st, &ct);
        __sincosf(ph, &sp, &cp);
        f2* o = spre + 5 + t * 9;
        o[0] = f2dup(cp * ct); o[1] = f2dup(sp * ct); o[2] = f2dup(-sp * ct);
        o[3] = f2dup(cp * st); o[4] = f2dup(sp * st); o[5] = f2dup(-sp * st);
        o[6] = f2dup(ct);      o[7] = f2dup(st);      o[8] = f2dup(-st);
    } else if (t == 4) {
        float st0, ct0, st2, ct2, st3, ct3;
        __sincosf(__ldg(pth + 0), &st0, &ct0);
        __sincosf(__ldg(pth + 2), &st2, &ct2);
        __sincosf(__ldg(pth + 3), &st3, &ct3);
        spre[0] = f2dup(ct0);
        spre[1] = f2dup(ct2 * st0);
        spre[2] = f2dup(st2 * st0);
        spre[3] = f2dup(ct3);
        spre[4] = f2dup(st3);
    }

    // ---- load 2 rows of x (24 contiguous floats) + k/b, compute xs ----
    float xa[12], xb[12];
    {
        float4 kv[3], bv[3], xv[6];
        kv[0] = __ldg((const float4*)(ink + 0));
        kv[1] = __ldg((const float4*)(ink + 4));
        kv[2] = __ldg((const float4*)(ink + 8));
        bv[0] = __ldg((const float4*)(inb + 0));
        bv[1] = __ldg((const float4*)(inb + 4));
        bv[2] = __ldg((const float4*)(inb + 8));
        if (r0 + 2 <= batch) {
            const float4* xp = (const float4*)(x + (size_t)r0 * 12);
#pragma unroll
            for (int i = 0; i < 6; i++) xv[i] = xp[i];
        } else {
#pragma unroll
            for (int i = 0; i < 6; i++) xv[i] = make_float4(0.f, 0.f, 0.f, 0.f);
            if (r0 < batch) {
                const float4* xp = (const float4*)(x + (size_t)r0 * 12);
                xv[0] = xp[0]; xv[1] = xp[1]; xv[2] = xp[2];
            }
        }
        const float* kk = (const float*)kv;
        const float* bb = (const float*)bv;
        const float* xf = (const float*)xv;
#pragma unroll
        for (int i = 0; i < 12; i++) {
            xa[i] = fmaf(xf[i],      kk[i], bb[i]);
            xb[i] = fmaf(xf[i + 12], kk[i], bb[i]);
        }
    }

    __syncthreads();   // spre ready

    // load MC from shared (broadcast LDS)
    auto ldmc = [&](int off) {
        const f2* p = spre + off;
        MC m;
        m.ar = p[0]; m.ai = p[1]; m.nai = p[2];
        m.cr = p[3]; m.ci = p[4]; m.nci = p[5];
        m.ct = p[6]; m.st = p[7]; m.nst = p[8];
        return m;
    };

    f2 U0 = spre[0], U1 = spre[1], U2 = spre[2];
    f2 V3 = spre[3], V4 = spre[4];

    C2 A0, A1, A2, A3, A4, A5;     // column 0
    C2 B1, B2, B3, B4, B5;         // column 3 (B0 stays real)
    f2 B0r, B1r, B2r, B3r;

    // mode4 [0,1] (data): c0 rows (u0,u1) real-real -> complex
    {
        MC m = mkmc(xa[3], xb[3], xa[0], xb[0]);
        A0.r = f2fma(m.ar, U0, f2mul(m.nst, U1)); A0.i = f2mul(m.ai, U0);
        A1.r = f2fma(m.cr, U0, f2mul(m.ct,  U1)); A1.i = f2mul(m.ci, U0);
    }
    // mode5 [2,3] (data): c0 (u2, 0); c3 (0, v3)
    {
        MC m = mkmc(xa[4], xb[4], xa[1], xb[1]);
        A2.r = f2mul(m.ar, U2); A2.i = f2mul(m.ai, U2);
        A3.r = f2mul(m.cr, U2); A3.i = f2mul(m.ci, U2);
        B2r = f2mul(m.nst, V3); B3r = f2mul(m.ct, V3);
    }
    // mode6 [4,5] (data): c3 (v4, 0)
    {
        MC m = mkmc(xa[5], xb[5], xa[2], xb[2]);
        B4.r = f2mul(m.ar, V4); B4.i = f2mul(m.ai, V4);
        B5.r = f2mul(m.cr, V4); B5.i = f2mul(m.ci, V4);
    }
    // mode7 [1,2] (uniform): c0 full; c3 (0, B2r real) -> stays real
    {
        MC u = ldmc(5);
        rot_cc(A1, A2, u);
        B1r = f2mul(u.nst, B2r);
        B2r = f2mul(u.ct,  B2r);
    }
    // mode8 [3,4] (uniform): c0 (A3 complex, 0); c3 (B3r real, B4 complex)
    {
        MC u = ldmc(14);
        rot_c0(A3, A4, u);
        rot_rc(B3r, B3, B4, u);
    }
    // mode9 [0,1] (data): c0 full; c3 (0, B1r real) -> stays real
    {
        MC m = mkmc(xa[9], xb[9], xa[6], xb[6]);
        rot_cc(A0, A1, m);
        B0r = f2mul(m.nst, B1r);
        B1r = f2mul(m.ct,  B1r);
    }
    // mode10 [2,3] (data): c0 full; c3 (B2r real, B3 complex)
    {
        MC m = mkmc(xa[10], xb[10], xa[7], xb[7]);
        rot_cc(A2, A3, m);
        rot_rc(B2r, B2, B3, m);
    }
    // mode11 [4,5] (data): c0 (A4 complex, 0); c3 full
    {
        MC m = mkmc(xa[11], xb[11], xa[8], xb[8]);
        rot_c0(A4, A5, m);
        rot_cc(B4, B5, m);
    }
    // mode12 [1,2] (uniform): c0 full; c3 (B1r real, B2 complex)
    {
        MC u = ldmc(23);
        rot_cc(A1, A2, u);
        rot_rc(B1r, B1, B2, u);
    }
    // mode13 [3,4] (uniform): c0 full; c3 full
    {
        MC u = ldmc(32);
        rot_cc(A3, A4, u);
        rot_cc(B3, B4, u);
    }

    // ---- 15 pair amplitudes (packed) ----
    f2 ZERO = f2dup(0.f);
    f2 a_r[6] = {A0.r, A1.r, A2.r, A3.r, A4.r, A5.r};
    f2 a_i[6] = {A0.i, A1.i, A2.i, A3.i, A4.i, A5.i};
    f2 b_r[6] = {B0r,  B1.r, B2.r, B3.r, B4.r, B5.r};
    f2 b_i[6] = {ZERO, B1.i, B2.i, B3.i, B4.i, B5.i};

    const int PA[15] = {0, 0, 0, 0, 0, 1, 1, 1, 1, 2, 2, 2, 3, 3, 4};
    const int PB[15] = {1, 2, 3, 4, 5, 2, 3, 4, 5, 3, 4, 5, 4, 5, 5};
    f2 mag[15];
    f2 sum = ZERO;
#pragma unroll
    for (int p = 0; p < 15; p++) {
        const int i = PA[p], j = PB[p];
        // re = (ar_i*br_j + ar_j*br_i) - (ai_i*bi_j + ai_j*bi_i)
        f2 re = f2sub(f2fma(a_r[i], b_r[j], f2mul(a_r[j], b_r[i])),
                      f2fma(a_i[i], b_i[j], f2mul(a_i[j], b_i[i])));
        // im = ar_i*bi_j + ai_i*br_j + ar_j*bi_i + ai_j*br_i
        f2 im = f2fma(a_r[i], b_i[j],
                 f2fma(a_i[i], b_r[j],
                  f2fma(a_r[j], b_i[i], f2mul(a_i[j], b_r[i]))));
        mag[p] = f2fma(re, re, f2mul(im, im));
        sum = f2add(sum, mag[p]);
    }

    float sa, sb;
    f2unpack(sum, sa, sb);
    float rna = frsqrt_ap(fmaxf(sa, 1e-24f));
    float rnb = frsqrt_ap(fmaxf(sb, 1e-24f));

#pragma unroll
    for (int p = 0; p < 15; p++) {
        float ma, mb;
        f2unpack(mag[p], ma, mb);
        sout[30 * t + p]      = fsqrt_ap(ma) * rna;
        sout[30 * t + 15 + p] = fsqrt_ap(mb) * rnb;
    }

    __syncthreads();

    // ---- coalesced copy-out ----
    int rows = batch - base;
    if (rows > TPB * 2) rows = TPB * 2;
    float* gout = out + (size_t)base * 15;
    if (rows == TPB * 2) {
        const float4* s4 = (const float4*)sout;
        float4* g4 = (float4*)gout;
#pragma unroll
        for (int q = 0; q < 8; q++) {
            int idx = t + q * TPB;
            if (idx < (TPB * 30) / 4) g4[idx] = s4[idx];
        }
    } else if (rows > 0) {
        for (int idx = t; idx < rows * 15; idx += TPB) gout[idx] = sout[idx];
    }
}

extern "C" void kernel_launch(void* const* d_in, const int* in_sizes, int n_in,
                              void* d_out, int out_size) {
    const float* x    = (const float*)d_in[0];
    const float* pphi = (const float*)d_in[1];
    const float* pth  = (const float*)d_in[2];
    const float* ink  = (const float*)d_in[3];
    const float* inb  = (const float*)d_in[4];
    float* out = (float*)d_out;

    int batch = in_sizes[0] / 12;
    int grid  = (batch + TPB * 2 - 1) / (TPB * 2);
    bqnn_main<<<grid, TPB>>>(x, pphi, pth, ink, inb, out, batch);
}

// round 6
// speedup vs baseline: 1.0269x; 1.0269x over previous
#include <cuda_runtime.h>

#define TPB 128   // one batch row per thread

__device__ __forceinline__ float fsqrt_ap(float x) {
    float r; asm("sqrt.approx.f32 %0,%1;" : "=f"(r) : "f"(x)); return r;
}
__device__ __forceinline__ float frsqrt_ap(float x) {
    float r; asm("rsqrt.approx.f32 %0,%1;" : "=f"(r) : "f"(x)); return r;
}

struct C { float r, i; };
struct MC { float ar, ai, cr, ci, ct, st; };

__device__ __forceinline__ MC mkmc(float th, float ph) {
    float st, ct, sp, cp;
    __sincosf(th, &st, &ct);
    __sincosf(ph, &sp, &cp);
    MC m;
    m.ct = ct; m.st = st;
    m.ar = cp * ct; m.ai = sp * ct;
    m.cr = cp * st; m.ci = sp * st;
    return m;
}

// full complex-complex Givens rotation (scalar; negations are free operand mods)
__device__ __forceinline__ void rot_cc(C& pi, C& pj, const MC& m) {
    float nir = fmaf(m.ar, pi.r, fmaf(-m.ai, pi.i, -m.st * pj.r));
    float nii = fmaf(m.ar, pi.i, fmaf( m.ai, pi.r, -m.st * pj.i));
    float njr = fmaf(m.cr, pi.r, fmaf(-m.ci, pi.i,  m.ct * pj.r));
    float nji = fmaf(m.cr, pi.i, fmaf( m.ci, pi.r,  m.ct * pj.i));
    pi.r = nir; pi.i = nii; pj.r = njr; pj.i = nji;
}
// pi complex, pj == 0 -> both complex
__device__ __forceinline__ void rot_c0(C& pi, C& pj, const MC& m) {
    float nir = fmaf(m.ar, pi.r, -m.ai * pi.i);
    float nii = fmaf(m.ar, pi.i,  m.ai * pi.r);
    pj.r      = fmaf(m.cr, pi.r, -m.ci * pi.i);
    pj.i      = fmaf(m.cr, pi.i,  m.ci * pi.r);
    pi.r = nir; pi.i = nii;
}
// pi real w, pj complex -> both complex
__device__ __forceinline__ void rot_rc(float w, C& pi, C& pj, const MC& m) {
    pi.r = fmaf(m.ar, w, -m.st * pj.r);
    pi.i = fmaf(m.ai, w, -m.st * pj.i);
    float njr = fmaf(m.cr, w, m.ct * pj.r);
    float nji = fmaf(m.ci, w, m.ct * pj.i);
    pj.r = njr; pj.i = nji;
}

__global__ __launch_bounds__(TPB, 10)
void bqnn_main(const float* __restrict__ x,
               const float* __restrict__ pphi,
               const float* __restrict__ pth,
               const float* __restrict__ ink,
               const float* __restrict__ inb,
               float* __restrict__ out,
               int batch) {
    __shared__ float sout[TPB * 15];
    __shared__ float spre[5 + 4 * 6];   // prelude u0,u1,u2,v3,v4; 4 uniform MCs of 6
    const int t = threadIdx.x;
    const int base = blockIdx.x * TPB;
    const int row = base + t;

    // ---- per-block uniform precompute (threads 0..4) ----
    if (t < 4) {
        float th = __ldg(pth + 4 + t), ph = __ldg(pphi + t);
        float st, ct, sp, cp;
        __sincosf(th, &st, &ct);
        __sincosf(ph, &sp, &cp);
        float* o = spre + 5 + t * 6;
        o[0] = cp * ct; o[1] = sp * ct;
        o[2] = cp * st; o[3] = sp * st;
        o[4] = ct;      o[5] = st;
    } else if (t == 4) {
        float st0, ct0, st2, ct2, st3, ct3;
        __sincosf(__ldg(pth + 0), &st0, &ct0);
        __sincosf(__ldg(pth + 2), &st2, &ct2);
        __sincosf(__ldg(pth + 3), &st3, &ct3);
        spre[0] = ct0;
        spre[1] = ct2 * st0;
        spre[2] = st2 * st0;
        spre[3] = ct3;
        spre[4] = st3;
    }

    // ---- load x row (3x float4) + k/b, compute xs ----
    float xs[12];
    {
        float4 kv[3], bv[3], xv[3];
        kv[0] = __ldg((const float4*)(ink + 0));
        kv[1] = __ldg((const float4*)(ink + 4));
        kv[2] = __ldg((const float4*)(ink + 8));
        bv[0] = __ldg((const float4*)(inb + 0));
        bv[1] = __ldg((const float4*)(inb + 4));
        bv[2] = __ldg((const float4*)(inb + 8));
        if (row < batch) {
            const float4* xp = (const float4*)(x + (size_t)row * 12);
            xv[0] = xp[0]; xv[1] = xp[1]; xv[2] = xp[2];
        } else {
            xv[0] = xv[1] = xv[2] = make_float4(0.f, 0.f, 0.f, 0.f);
        }
        const float* kk = (const float*)kv;
        const float* bb = (const float*)bv;
        const float* xf = (const float*)xv;
#pragma unroll
        for (int i = 0; i < 12; i++) xs[i] = fmaf(xf[i], kk[i], bb[i]);
    }

    __syncthreads();   // spre ready

    auto ldmc = [&](int q) {
        const float* p = spre + 5 + q * 6;
        MC m;
        m.ar = p[0]; m.ai = p[1];
        m.cr = p[2]; m.ci = p[3];
        m.ct = p[4]; m.st = p[5];
        return m;
    };

    float U0 = spre[0], U1 = spre[1], U2 = spre[2];
    float V3 = spre[3], V4 = spre[4];

    C A0, A1, A2, A3, A4, A5;     // column 0
    C B1, B2, B3, B4, B5;         // column 3 (B0 stays real)
    float B0r, B1r, B2r, B3r;

    // mode4 [0,1] (data): c0 rows (u0,u1) real -> complex
    {
        MC m = mkmc(xs[3], xs[0]);
        A0.r = fmaf(m.ar, U0, -m.st * U1); A0.i = m.ai * U0;
        A1.r = fmaf(m.cr, U0,  m.ct * U1); A1.i = m.ci * U0;
    }
    // mode5 [2,3] (data): c0 (u2, 0); c3 (0, v3)
    {
        MC m = mkmc(xs[4], xs[1]);
        A2.r = m.ar * U2; A2.i = m.ai * U2;
        A3.r = m.cr * U2; A3.i = m.ci * U2;
        B2r = -m.st * V3; B3r = m.ct * V3;
    }
    // mode6 [4,5] (data): c3 (v4, 0)
    {
        MC m = mkmc(xs[5], xs[2]);
        B4.r = m.ar * V4; B4.i = m.ai * V4;
        B5.r = m.cr * V4; B5.i = m.ci * V4;
    }
    // mode7 [1,2] (uniform q0): c0 full; c3 (0, B2r real) -> stays real
    {
        MC u = ldmc(0);
        rot_cc(A1, A2, u);
        B1r = -u.st * B2r;
        B2r =  u.ct * B2r;
    }
    // mode8 [3,4] (uniform q1): c0 (A3, 0); c3 (B3r real, B4 complex)
    {
        MC u = ldmc(1);
        rot_c0(A3, A4, u);
        rot_rc(B3r, B3, B4, u);
    }
    // mode9 [0,1] (data): c0 full; c3 (0, B1r real) -> stays real
    {
        MC m = mkmc(xs[9], xs[6]);
        rot_cc(A0, A1, m);
        B0r = -m.st * B1r;
        B1r =  m.ct * B1r;
    }
    // mode10 [2,3] (data): c0 full; c3 (B2r real, B3 complex)
    {
        MC m = mkmc(xs[10], xs[7]);
        rot_cc(A2, A3, m);
        rot_rc(B2r, B2, B3, m);
    }
    // mode11 [4,5] (data): c0 (A4, 0); c3 full
    {
        MC m = mkmc(xs[11], xs[8]);
        rot_c0(A4, A5, m);
        rot_cc(B4, B5, m);
    }
    // mode12 [1,2] (uniform q2): c0 full; c3 (B1r real, B2 complex)
    {
        MC u = ldmc(2);
        rot_cc(A1, A2, u);
        rot_rc(B1r, B1, B2, u);
    }
    // mode13 [3,4] (uniform q3): c0 full; c3 full
    {
        MC u = ldmc(3);
        rot_cc(A3, A4, u);
        rot_cc(B3, B4, u);
    }

    // ---- 15 pair amplitudes; store unnormalized |amp| to smem ----
    float a_r[6] = {A0.r, A1.r, A2.r, A3.r, A4.r, A5.r};
    float a_i[6] = {A0.i, A1.i, A2.i, A3.i, A4.i, A5.i};
    float b_r[6] = {B0r,  B1.r, B2.r, B3.r, B4.r, B5.r};
    float b_i[6] = {0.f,  B1.i, B2.i, B3.i, B4.i, B5.i};

    const int PA[15] = {0, 0, 0, 0, 0, 1, 1, 1, 1, 2, 2, 2, 3, 3, 4};
    const int PB[15] = {1, 2, 3, 4, 5, 2, 3, 4, 5, 3, 4, 5, 4, 5, 5};
    float sum = 0.f;
#pragma unroll
    for (int p = 0; p < 15; p++) {
        const int i = PA[p], j = PB[p];
        float re = fmaf(a_r[i], b_r[j],
                    fmaf(-a_i[i], b_i[j],
                     fmaf(a_r[j], b_r[i], -a_i[j] * b_i[i])));
        float im = fmaf(a_r[i], b_i[j],
                    fmaf(a_i[i], b_r[j],
                     fmaf(a_r[j], b_i[i], a_i[j] * b_r[i])));
        float mag = fmaf(re, re, im * im);
        sum += mag;
        sout[15 * t + p] = fsqrt_ap(mag);
    }

    // in-place normalize (stride-15 => conflict-free across the warp)
    {
        float rn = frsqrt_ap(fmaxf(sum, 1e-24f));
#pragma unroll
        for (int p = 0; p < 15; p++) sout[15 * t + p] *= rn;
    }

    __syncthreads();

    // ---- coalesced copy-out ----
    int rows = batch - base;
    if (rows > TPB) rows = TPB;
    float* gout = out + (size_t)base * 15;
    if (rows == TPB) {
        const float4* s4 = (const float4*)sout;
        float4* g4 = (float4*)gout;
#pragma unroll
        for (int q = 0; q < 4; q++) {
            int idx = t + q * TPB;
            if (idx < (TPB * 15) / 4) g4[idx] = s4[idx];
        }
    } else if (rows > 0) {
        for (int idx = t; idx < rows * 15; idx += TPB) gout[idx] = sout[idx];
    }
}

extern "C" void kernel_launch(void* const* d_in, const int* in_sizes, int n_in,
                              void* d_out, int out_size) {
    const float* x    = (const float*)d_in[0];
    const float* pphi = (const float*)d_in[1];
    const float* pth  = (const float*)d_in[2];
    const float* ink  = (const float*)d_in[3];
    const float* inb  = (const float*)d_in[4];
    float* out = (float*)d_out;

    int batch = in_sizes[0] / 12;
    int grid  = (batch + TPB - 1) / TPB;
    bqnn_main<<<grid, TPB>>>(x, pphi, pth, ink, inb, out, batch);
}